// round 1
// baseline (speedup 1.0000x reference)
#include <cuda_runtime.h>
#include <math.h>

// Problem constants (shapes fixed by the dataset)
#define NN 100000
#define EE 600000
#define D  128
#define KK 256   // concat-K: [mean | x] against [W_l ; W_r]

// Scratch (allocation-free rule: __device__ globals)
__device__ float g_agg[(size_t)NN * D];
__device__ float g_cnt[NN];
__device__ float g_h[(size_t)NN * D];
__device__ float g_bnsum[D];
__device__ float g_bnsumsq[D];
__device__ float g_scale[D];
__device__ float g_shift[D];

// ---------------------------------------------------------------------------
// Edge scatter: one warp per edge. Feature-contiguous lane mapping so each
// RED.f32 instruction covers a contiguous 128B span of the dst row.
// ---------------------------------------------------------------------------
__global__ void scatter_kernel(const float* __restrict__ feat,
                               const int* __restrict__ ei,
                               int E, int addCnt)
{
    int gw   = (blockIdx.x * blockDim.x + threadIdx.x) >> 5;
    int lane = threadIdx.x & 31;
    if (gw >= E) return;
    int s = ei[gw];         // src
    int d = ei[E + gw];     // dst
    const float* f = feat + (size_t)s * D;
    float* a = g_agg + (size_t)d * D;
#pragma unroll
    for (int i = 0; i < 4; i++)
        atomicAdd(a + i * 32 + lane, __ldg(f + i * 32 + lane));
    if (addCnt && lane == 0)
        atomicAdd(g_cnt + d, 1.0f);
}

// ---------------------------------------------------------------------------
// Fused SAGE layer:  out = [agg*invc | xin] @ [Wl ; Wr] + b
// then row-wise L2 normalize. LAYER==1: relu, store h_pre, accumulate BN
// sum/sumsq. LAYER==2: store embed to d_out, compute fc preds.
// 256 threads, 128x128 output tile, 8x8 register tile per thread.
// ---------------------------------------------------------------------------
template <int LAYER>
__global__ __launch_bounds__(256, 2)
void sage_kernel(const float* __restrict__ xin,
                 const float* __restrict__ Wl,
                 const float* __restrict__ Wr,
                 const float* __restrict__ bias,
                 const float* __restrict__ fcW,
                 const float* __restrict__ fcb,
                 float* __restrict__ outh,    // layer1: h_pre
                 float* __restrict__ oute,    // layer2: embed (d_out + N)
                 float* __restrict__ outp,    // layer2: preds (d_out)
                 int Nn)
{
    __shared__ float As[D][17];     // A' tile [row][kk], padded vs bank conflicts
    __shared__ float Bs[16][D];     // B' tile [kk][col]
    __shared__ float RowInv[D];     // first inv_cnt, later inv_norm

    const int tid = threadIdx.x;
    const int tx = tid & 15;        // col group: cols tx + j*16
    const int ty = tid >> 4;        // row group: rows ty*8 + i
    const int row0 = blockIdx.x * D;

    if (tid < D) {
        int r = row0 + tid;
        RowInv[tid] = (r < Nn) ? (1.0f / fmaxf(g_cnt[r], 1.0f)) : 0.0f;
    }
    __syncthreads();

    float acc[8][8];
#pragma unroll
    for (int i = 0; i < 8; i++)
#pragma unroll
        for (int j = 0; j < 8; j++) acc[i][j] = 0.f;

    const int lr  = tid >> 1;        // row this thread loads for A
    const int kk0 = (tid & 1) * 8;   // k sub-offset
    const int grow = row0 + lr;
    const bool rok = grow < Nn;
    const float ic = RowInv[lr];     // inv_cnt for the row this thread loads

    const int bkk = tid >> 4;        // B tile row this thread loads
    const int bc  = tx * 8;          // B tile col base

    for (int kc = 0; kc < KK; kc += 16) {
        float av[8];
        if (rok) {
            if (kc < D) {
                const float4* p = (const float4*)(g_agg + (size_t)grow * D + kc + kk0);
                float4 v0 = p[0], v1 = p[1];
                av[0] = v0.x * ic; av[1] = v0.y * ic; av[2] = v0.z * ic; av[3] = v0.w * ic;
                av[4] = v1.x * ic; av[5] = v1.y * ic; av[6] = v1.z * ic; av[7] = v1.w * ic;
            } else {
                const float4* p = (const float4*)(xin + (size_t)grow * D + (kc - D) + kk0);
                float4 v0 = p[0], v1 = p[1];
                av[0] = v0.x; av[1] = v0.y; av[2] = v0.z; av[3] = v0.w;
                av[4] = v1.x; av[5] = v1.y; av[6] = v1.z; av[7] = v1.w;
            }
        } else {
#pragma unroll
            for (int i = 0; i < 8; i++) av[i] = 0.f;
        }
        int bk = kc + bkk;
        const float* wsrc = (bk < D) ? (Wl + (size_t)bk * D + bc)
                                     : (Wr + (size_t)(bk - D) * D + bc);
        float4 b0 = ((const float4*)wsrc)[0];
        float4 b1 = ((const float4*)wsrc)[1];

        __syncthreads();
#pragma unroll
        for (int i = 0; i < 8; i++) As[lr][kk0 + i] = av[i];
        *((float4*)&Bs[bkk][bc])     = b0;
        *((float4*)&Bs[bkk][bc + 4]) = b1;
        __syncthreads();

#pragma unroll
        for (int kk = 0; kk < 16; kk++) {
            float a[8], b[8];
#pragma unroll
            for (int i = 0; i < 8; i++) a[i] = As[ty * 8 + i][kk];
#pragma unroll
            for (int j = 0; j < 8; j++) b[j] = Bs[kk][tx + j * 16];
#pragma unroll
            for (int i = 0; i < 8; i++)
#pragma unroll
                for (int j = 0; j < 8; j++)
                    acc[i][j] = fmaf(a[i], b[j], acc[i][j]);
        }
    }

    // + bias
#pragma unroll
    for (int j = 0; j < 8; j++) {
        float bb = bias[tx + j * 16];
#pragma unroll
        for (int i = 0; i < 8; i++) acc[i][j] += bb;
    }

    // row-wise L2 norm: partial sumsq -> smem reduce
    __syncthreads();
#pragma unroll
    for (int i = 0; i < 8; i++) {
        float s = 0.f;
#pragma unroll
        for (int j = 0; j < 8; j++) s = fmaf(acc[i][j], acc[i][j], s);
        As[ty * 8 + i][tx] = s;
    }
    __syncthreads();
    if (tid < D) {
        float s = 0.f;
#pragma unroll
        for (int t = 0; t < 16; t++) s += As[tid][t];
        RowInv[tid] = 1.0f / fmaxf(sqrtf(s), 1e-12f);
    }
    __syncthreads();

    float val[8][8];
#pragma unroll
    for (int i = 0; i < 8; i++) {
        float iv = RowInv[ty * 8 + i];
        bool ok = (row0 + ty * 8 + i) < Nn;
#pragma unroll
        for (int j = 0; j < 8; j++) {
            float v = acc[i][j] * iv;
            if (LAYER == 1) v = fmaxf(v, 0.f);
            val[i][j] = ok ? v : 0.f;
        }
    }

    if (LAYER == 1) {
#pragma unroll
        for (int i = 0; i < 8; i++) {
            int r = row0 + ty * 8 + i;
            if (r < Nn) {
#pragma unroll
                for (int j = 0; j < 8; j++)
                    outh[(size_t)r * D + tx + j * 16] = val[i][j];
            }
        }
        // BN column sums (per-block partial -> atomic)
        __syncthreads();
#pragma unroll
        for (int j = 0; j < 8; j++) {
            float s = 0.f;
#pragma unroll
            for (int i = 0; i < 8; i++) s += val[i][j];
            Bs[ty][tx + j * 16] = s;
        }
        __syncthreads();
        if (tid < D) {
            float s = 0.f;
#pragma unroll
            for (int t = 0; t < 16; t++) s += Bs[t][tid];
            atomicAdd(g_bnsum + tid, s);
        }
        __syncthreads();
#pragma unroll
        for (int j = 0; j < 8; j++) {
            float s = 0.f;
#pragma unroll
            for (int i = 0; i < 8; i++) s = fmaf(val[i][j], val[i][j], s);
            Bs[ty][tx + j * 16] = s;
        }
        __syncthreads();
        if (tid < D) {
            float s = 0.f;
#pragma unroll
            for (int t = 0; t < 16; t++) s += Bs[t][tid];
            atomicAdd(g_bnsumsq + tid, s);
        }
    } else {
#pragma unroll
        for (int i = 0; i < 8; i++) {
            int r = row0 + ty * 8 + i;
            if (r < Nn) {
#pragma unroll
                for (int j = 0; j < 8; j++)
                    oute[(size_t)r * D + tx + j * 16] = val[i][j];
            }
        }
        // preds = embed[:, :64] @ fcW + fcb  (cols tx + j*16, j<4 => col < 64)
        float fw[4];
#pragma unroll
        for (int j = 0; j < 4; j++) fw[j] = fcW[tx + j * 16];
        __syncthreads();
#pragma unroll
        for (int i = 0; i < 8; i++) {
            float s = 0.f;
#pragma unroll
            for (int j = 0; j < 4; j++) s = fmaf(val[i][j], fw[j], s);
            As[ty * 8 + i][tx] = s;
        }
        __syncthreads();
        if (tid < D) {
            int r = row0 + tid;
            if (r < Nn) {
                float s = 0.f;
#pragma unroll
                for (int t = 0; t < 16; t++) s += As[tid][t];
                outp[r] = s + fcb[0];
            }
        }
    }
}

// ---------------------------------------------------------------------------
__global__ void bnstat_kernel(const float* __restrict__ gamma,
                              const float* __restrict__ beta, float invN)
{
    int c = threadIdx.x;
    float mu  = g_bnsum[c] * invN;
    float var = g_bnsumsq[c] * invN - mu * mu;
    float s = gamma[c] * rsqrtf(var + 1e-5f);
    g_scale[c] = s;
    g_shift[c] = beta[c] - mu * s;
}

__global__ void bnapply_kernel(int n4)
{
    int i = blockIdx.x * blockDim.x + threadIdx.x;
    if (i >= n4) return;
    float4 v = ((float4*)g_h)[i];
    int c = (i & 31) * 4;
    v.x = fmaf(v.x, g_scale[c],     g_shift[c]);
    v.y = fmaf(v.y, g_scale[c + 1], g_shift[c + 1]);
    v.z = fmaf(v.z, g_scale[c + 2], g_shift[c + 2]);
    v.w = fmaf(v.w, g_scale[c + 3], g_shift[c + 3]);
    ((float4*)g_h)[i] = v;
}

// ---------------------------------------------------------------------------
extern "C" void kernel_launch(void* const* d_in, const int* in_sizes, int n_in,
                              void* d_out, int out_size)
{
    const float* x   = (const float*)d_in[0];
    const int*   ei  = (const int*)  d_in[1];
    const float* W1l = (const float*)d_in[2];
    const float* b1l = (const float*)d_in[3];
    const float* W1r = (const float*)d_in[4];
    const float* bng = (const float*)d_in[5];
    const float* bnb = (const float*)d_in[6];
    const float* W2l = (const float*)d_in[7];
    const float* b2l = (const float*)d_in[8];
    const float* W2r = (const float*)d_in[9];
    const float* fcW = (const float*)d_in[10];
    const float* fcb = (const float*)d_in[11];

    int Nn = in_sizes[0] / D;
    int E  = in_sizes[1] / 2;

    float* out   = (float*)d_out;
    float* pred  = out;          // [N]
    float* embed = out + Nn;     // [N,128]

    void *agg_p, *cnt_p, *sum_p, *sq_p, *h_pv;
    cudaGetSymbolAddress(&agg_p, g_agg);
    cudaGetSymbolAddress(&cnt_p, g_cnt);
    cudaGetSymbolAddress(&sum_p, g_bnsum);
    cudaGetSymbolAddress(&sq_p,  g_bnsumsq);
    cudaGetSymbolAddress(&h_pv,  g_h);
    float* h_p = (float*)h_pv;

    cudaMemsetAsync(agg_p, 0, (size_t)Nn * D * sizeof(float), 0);
    cudaMemsetAsync(cnt_p, 0, (size_t)Nn * sizeof(float), 0);
    cudaMemsetAsync(sum_p, 0, D * sizeof(float), 0);
    cudaMemsetAsync(sq_p,  0, D * sizeof(float), 0);

    const int sthreads = 256;
    const int sblocks  = (E * 32 + sthreads - 1) / sthreads;
    scatter_kernel<<<sblocks, sthreads>>>(x, ei, E, 1);

    const int gblocks = (Nn + D - 1) / D;
    sage_kernel<1><<<gblocks, 256>>>(x, W1l, W1r, b1l, nullptr, nullptr,
                                     h_p, nullptr, nullptr, Nn);

    bnstat_kernel<<<1, D>>>(bng, bnb, 1.0f / (float)Nn);

    const int n4 = Nn * D / 4;
    bnapply_kernel<<<(n4 + 255) / 256, 256>>>(n4);

    cudaMemsetAsync(agg_p, 0, (size_t)Nn * D * sizeof(float), 0);
    scatter_kernel<<<sblocks, sthreads>>>(h_p, ei, E, 0);

    sage_kernel<2><<<gblocks, 256>>>(h_p, W2l, W2r, b2l, fcW, fcb,
                                     nullptr, embed, pred, Nn);
}

// round 7
// speedup vs baseline: 1.0500x; 1.0500x over previous
#include <cuda_runtime.h>
#include <math.h>

// Problem constants (shapes fixed by the dataset)
#define NN 100000
#define EE 600000
#define D  128
#define KK 256   // concat-K: [mean | x] against [W_l ; W_r]

// Scratch (allocation-free rule: __device__ globals)
__device__ float g_agg[(size_t)NN * D];
__device__ float g_cnt[NN];
__device__ float g_h[(size_t)NN * D];
__device__ float g_bnsum[D];
__device__ float g_bnsumsq[D];
__device__ float g_scale[D];
__device__ float g_shift[D];

// ---------------------------------------------------------------------------
// Edge scatter: one warp per edge, one float4 per lane (128 floats/row).
// Uses red.global.add.v4.f32 (sm_90+) — 1 vector RED per lane instead of 4
// scalar REDs. USE_BN: apply BatchNorm scale/shift to the gathered feature
// before scattering (fuses bnapply into the layer-2 scatter).
// ---------------------------------------------------------------------------
template <int USE_BN>
__global__ void scatter_kernel(const float* __restrict__ feat,
                               const int* __restrict__ ei,
                               int E, int addCnt)
{
    int gw   = (blockIdx.x * blockDim.x + threadIdx.x) >> 5;
    int lane = threadIdx.x & 31;
    if (gw >= E) return;
    int s = ei[gw];         // src
    int d = ei[E + gw];     // dst

    float4 v = __ldg((const float4*)(feat + (size_t)s * D) + lane);
    if (USE_BN) {
        int c = lane * 4;
        v.x = fmaf(v.x, g_scale[c],     g_shift[c]);
        v.y = fmaf(v.y, g_scale[c + 1], g_shift[c + 1]);
        v.z = fmaf(v.z, g_scale[c + 2], g_shift[c + 2]);
        v.w = fmaf(v.w, g_scale[c + 3], g_shift[c + 3]);
    }
    float* a = g_agg + (size_t)d * D + lane * 4;
    asm volatile("red.global.add.v4.f32 [%0], {%1, %2, %3, %4};"
                 :: "l"(a), "f"(v.x), "f"(v.y), "f"(v.z), "f"(v.w)
                 : "memory");
    if (addCnt && lane == 0)
        atomicAdd(g_cnt + d, 1.0f);
}

// ---------------------------------------------------------------------------
// Fused SAGE layer:  out = [agg*invc | xin'] @ [Wl ; Wr] + b
// (LAYER==2: xin' = BN(xin) applied on the fly from g_scale/g_shift)
// then row-wise L2 normalize. LAYER==1: relu, store h_pre, accumulate BN
// sum/sumsq. LAYER==2: store embed to d_out, compute fc preds.
// 256 threads, 128x128 output tile, 8x8 register tile per thread.
// A smem tile stored K-major [16][136] so the 8 a-loads are 2x LDS.128.
// ---------------------------------------------------------------------------
template <int LAYER>
__global__ __launch_bounds__(256, 2)
void sage_kernel(const float* __restrict__ xin,
                 const float* __restrict__ Wl,
                 const float* __restrict__ Wr,
                 const float* __restrict__ bias,
                 const float* __restrict__ fcW,
                 const float* __restrict__ fcb,
                 float* __restrict__ outh,    // layer1: h_pre
                 float* __restrict__ oute,    // layer2: embed (d_out + N)
                 float* __restrict__ outp,    // layer2: preds (d_out)
                 int Nn)
{
    __shared__ float AsT[16][136];  // A' tile [kk][row], padded
    __shared__ float Bs[16][D];     // B' tile [kk][col]
    __shared__ float RowInv[D];     // first inv_cnt, later inv_norm
    __shared__ float ScS[D], ShS[D];

    float* AsF = &AsT[0][0];        // epilogue scratch alias: [r*17+t], 2176 floats

    const int tid = threadIdx.x;
    const int tx = tid & 15;        // col group: cols tx + j*16
    const int ty = tid >> 4;        // row group: rows ty*8 + i
    const int row0 = blockIdx.x * D;

    if (tid < D) {
        int r = row0 + tid;
        RowInv[tid] = (r < Nn) ? (1.0f / fmaxf(g_cnt[r], 1.0f)) : 0.0f;
        if (LAYER == 2) { ScS[tid] = g_scale[tid]; ShS[tid] = g_shift[tid]; }
    }
    __syncthreads();

    float acc[8][8];
#pragma unroll
    for (int i = 0; i < 8; i++)
#pragma unroll
        for (int j = 0; j < 8; j++) acc[i][j] = 0.f;

    const int lr  = tid >> 1;        // row this thread loads for A
    const int kk0 = (tid & 1) * 8;   // k sub-offset
    const int grow = row0 + lr;
    const bool rok = grow < Nn;
    const float ic = RowInv[lr];     // inv_cnt for the row this thread loads

    const int bkk = tid >> 4;        // B tile row this thread loads
    const int bc  = tx * 8;          // B tile col base

    for (int kc = 0; kc < KK; kc += 16) {
        float av[8];
        if (rok) {
            if (kc < D) {
                const float4* p = (const float4*)(g_agg + (size_t)grow * D + kc + kk0);
                float4 v0 = p[0], v1 = p[1];
                av[0] = v0.x * ic; av[1] = v0.y * ic; av[2] = v0.z * ic; av[3] = v0.w * ic;
                av[4] = v1.x * ic; av[5] = v1.y * ic; av[6] = v1.z * ic; av[7] = v1.w * ic;
            } else {
                const float4* p = (const float4*)(xin + (size_t)grow * D + (kc - D) + kk0);
                float4 v0 = p[0], v1 = p[1];
                av[0] = v0.x; av[1] = v0.y; av[2] = v0.z; av[3] = v0.w;
                av[4] = v1.x; av[5] = v1.y; av[6] = v1.z; av[7] = v1.w;
                if (LAYER == 2) {
                    int c0 = kc - D + kk0;
#pragma unroll
                    for (int i = 0; i < 8; i++)
                        av[i] = fmaf(av[i], ScS[c0 + i], ShS[c0 + i]);
                }
            }
        } else {
#pragma unroll
            for (int i = 0; i < 8; i++) av[i] = 0.f;
        }
        int bk = kc + bkk;
        const float* wsrc = (bk < D) ? (Wl + (size_t)bk * D + bc)
                                     : (Wr + (size_t)(bk - D) * D + bc);
        float4 b0 = ((const float4*)wsrc)[0];
        float4 b1 = ((const float4*)wsrc)[1];

        __syncthreads();
#pragma unroll
        for (int i = 0; i < 8; i++) AsT[kk0 + i][lr] = av[i];
        *((float4*)&Bs[bkk][bc])     = b0;
        *((float4*)&Bs[bkk][bc + 4]) = b1;
        __syncthreads();

#pragma unroll
        for (int kk = 0; kk < 16; kk++) {
            float a[8], b[8];
            *((float4*)&a[0]) = *((const float4*)&AsT[kk][ty * 8]);
            *((float4*)&a[4]) = *((const float4*)&AsT[kk][ty * 8 + 4]);
#pragma unroll
            for (int j = 0; j < 8; j++) b[j] = Bs[kk][tx + j * 16];
#pragma unroll
            for (int i = 0; i < 8; i++)
#pragma unroll
                for (int j = 0; j < 8; j++)
                    acc[i][j] = fmaf(a[i], b[j], acc[i][j]);
        }
    }

    // + bias
#pragma unroll
    for (int j = 0; j < 8; j++) {
        float bb = bias[tx + j * 16];
#pragma unroll
        for (int i = 0; i < 8; i++) acc[i][j] += bb;
    }

    // row-wise L2 norm: partial sumsq -> smem reduce (scratch = AsF[r*17+t])
    __syncthreads();
#pragma unroll
    for (int i = 0; i < 8; i++) {
        float s = 0.f;
#pragma unroll
        for (int j = 0; j < 8; j++) s = fmaf(acc[i][j], acc[i][j], s);
        AsF[(ty * 8 + i) * 17 + tx] = s;
    }
    __syncthreads();
    if (tid < D) {
        float s = 0.f;
#pragma unroll
        for (int t = 0; t < 16; t++) s += AsF[tid * 17 + t];
        RowInv[tid] = 1.0f / fmaxf(sqrtf(s), 1e-12f);
    }
    __syncthreads();

    float val[8][8];
#pragma unroll
    for (int i = 0; i < 8; i++) {
        float iv = RowInv[ty * 8 + i];
        bool ok = (row0 + ty * 8 + i) < Nn;
#pragma unroll
        for (int j = 0; j < 8; j++) {
            float v = acc[i][j] * iv;
            if (LAYER == 1) v = fmaxf(v, 0.f);
            val[i][j] = ok ? v : 0.f;
        }
    }

    if (LAYER == 1) {
#pragma unroll
        for (int i = 0; i < 8; i++) {
            int r = row0 + ty * 8 + i;
            if (r < Nn) {
#pragma unroll
                for (int j = 0; j < 8; j++)
                    outh[(size_t)r * D + tx + j * 16] = val[i][j];
            }
        }
        // BN column sums (per-block partial -> atomic)
        __syncthreads();
#pragma unroll
        for (int j = 0; j < 8; j++) {
            float s = 0.f;
#pragma unroll
            for (int i = 0; i < 8; i++) s += val[i][j];
            Bs[ty][tx + j * 16] = s;
        }
        __syncthreads();
        if (tid < D) {
            float s = 0.f;
#pragma unroll
            for (int t = 0; t < 16; t++) s += Bs[t][tid];
            atomicAdd(g_bnsum + tid, s);
        }
        __syncthreads();
#pragma unroll
        for (int j = 0; j < 8; j++) {
            float s = 0.f;
#pragma unroll
            for (int i = 0; i < 8; i++) s = fmaf(val[i][j], val[i][j], s);
            Bs[ty][tx + j * 16] = s;
        }
        __syncthreads();
        if (tid < D) {
            float s = 0.f;
#pragma unroll
            for (int t = 0; t < 16; t++) s += Bs[t][tid];
            atomicAdd(g_bnsumsq + tid, s);
        }
    } else {
#pragma unroll
        for (int i = 0; i < 8; i++) {
            int r = row0 + ty * 8 + i;
            if (r < Nn) {
#pragma unroll
                for (int j = 0; j < 8; j++)
                    oute[(size_t)r * D + tx + j * 16] = val[i][j];
            }
        }
        // preds = embed[:, :64] @ fcW + fcb  (cols tx + j*16, j<4 => col < 64)
        float fw[4];
#pragma unroll
        for (int j = 0; j < 4; j++) fw[j] = fcW[tx + j * 16];
        __syncthreads();
#pragma unroll
        for (int i = 0; i < 8; i++) {
            float s = 0.f;
#pragma unroll
            for (int j = 0; j < 4; j++) s = fmaf(val[i][j], fw[j], s);
            AsF[(ty * 8 + i) * 17 + tx] = s;
        }
        __syncthreads();
        if (tid < D) {
            int r = row0 + tid;
            if (r < Nn) {
                float s = 0.f;
#pragma unroll
                for (int t = 0; t < 16; t++) s += AsF[tid * 17 + t];
                outp[r] = s + fcb[0];
            }
        }
    }
}

// ---------------------------------------------------------------------------
__global__ void bnstat_kernel(const float* __restrict__ gamma,
                              const float* __restrict__ beta, float invN)
{
    int c = threadIdx.x;
    float mu  = g_bnsum[c] * invN;
    float var = g_bnsumsq[c] * invN - mu * mu;
    float s = gamma[c] * rsqrtf(var + 1e-5f);
    g_scale[c] = s;
    g_shift[c] = beta[c] - mu * s;
}

// ---------------------------------------------------------------------------
extern "C" void kernel_launch(void* const* d_in, const int* in_sizes, int n_in,
                              void* d_out, int out_size)
{
    const float* x   = (const float*)d_in[0];
    const int*   ei  = (const int*)  d_in[1];
    const float* W1l = (const float*)d_in[2];
    const float* b1l = (const float*)d_in[3];
    const float* W1r = (const float*)d_in[4];
    const float* bng = (const float*)d_in[5];
    const float* bnb = (const float*)d_in[6];
    const float* W2l = (const float*)d_in[7];
    const float* b2l = (const float*)d_in[8];
    const float* W2r = (const float*)d_in[9];
    const float* fcW = (const float*)d_in[10];
    const float* fcb = (const float*)d_in[11];

    int Nn = in_sizes[0] / D;
    int E  = in_sizes[1] / 2;

    float* out   = (float*)d_out;
    float* pred  = out;          // [N]
    float* embed = out + Nn;     // [N,128]

    void *agg_p, *cnt_p, *sum_p, *sq_p, *h_pv;
    cudaGetSymbolAddress(&agg_p, g_agg);
    cudaGetSymbolAddress(&cnt_p, g_cnt);
    cudaGetSymbolAddress(&sum_p, g_bnsum);
    cudaGetSymbolAddress(&sq_p,  g_bnsumsq);
    cudaGetSymbolAddress(&h_pv,  g_h);
    float* h_p = (float*)h_pv;

    cudaMemsetAsync(agg_p, 0, (size_t)Nn * D * sizeof(float), 0);
    cudaMemsetAsync(cnt_p, 0, (size_t)Nn * sizeof(float), 0);
    cudaMemsetAsync(sum_p, 0, D * sizeof(float), 0);
    cudaMemsetAsync(sq_p,  0, D * sizeof(float), 0);

    const int sthreads = 256;                       // 8 warps / block
    const int sblocks  = (E + 7) / 8;
    scatter_kernel<0><<<sblocks, sthreads>>>(x, ei, E, 1);

    const int gblocks = (Nn + D - 1) / D;
    sage_kernel<1><<<gblocks, 256>>>(x, W1l, W1r, b1l, nullptr, nullptr,
                                     h_p, nullptr, nullptr, Nn);

    bnstat_kernel<<<1, D>>>(bng, bnb, 1.0f / (float)Nn);

    cudaMemsetAsync(agg_p, 0, (size_t)Nn * D * sizeof(float), 0);
    scatter_kernel<1><<<sblocks, sthreads>>>(h_p, ei, E, 0);  // BN fused in gather

    sage_kernel<2><<<gblocks, 256>>>(h_p, W2l, W2r, b2l, fcW, fcb,
                                     nullptr, embed, pred, Nn);
}

// round 9
// speedup vs baseline: 1.2816x; 1.2205x over previous
#include <cuda_runtime.h>
#include <math.h>

// Problem constants (shapes fixed by the dataset)
#define NN 100000
#define EE 600000
#define D  128
#define KK 256   // concat-K: [mean | x] against [W_l ; W_r]

// Scratch (allocation-free rule: __device__ globals)
__device__ float g_agg[(size_t)NN * D];
__device__ float g_h[(size_t)NN * D];
__device__ float g_bnsum[D];
__device__ float g_bnsumsq[D];
__device__ float g_scale[D];
__device__ float g_shift[D];
// CSR scratch
__device__ int g_dcnt[NN];
__device__ int g_rowptr[NN + 1];
__device__ int g_fill[NN];
__device__ int g_eidx[EE];
__device__ int g_partial[512];

// ---------------------------------------------------------------------------
// CSR build: histogram -> exclusive scan (3 kernels) -> fill
// ---------------------------------------------------------------------------
__global__ void hist_kernel(const int* __restrict__ ei, int E)
{
    int i = blockIdx.x * blockDim.x + threadIdx.x;
    if (i < E) atomicAdd(&g_dcnt[ei[E + i]], 1);
}

__global__ void scanA_kernel(int Nn)
{
    __shared__ int sh[256];
    int i = blockIdx.x * 256 + threadIdx.x;
    sh[threadIdx.x] = (i < Nn) ? g_dcnt[i] : 0;
    __syncthreads();
    for (int off = 128; off > 0; off >>= 1) {
        if (threadIdx.x < off) sh[threadIdx.x] += sh[threadIdx.x + off];
        __syncthreads();
    }
    if (threadIdx.x == 0) g_partial[blockIdx.x] = sh[0];
}

__global__ void scanB_kernel(int nb)   // single block, 512 threads
{
    __shared__ int sh[512];
    int t = threadIdx.x;
    int v = (t < nb) ? g_partial[t] : 0;
    sh[t] = v;
    __syncthreads();
    for (int off = 1; off < 512; off <<= 1) {
        int x = (t >= off) ? sh[t - off] : 0;
        __syncthreads();
        sh[t] += x;
        __syncthreads();
    }
    if (t < nb) g_partial[t] = sh[t] - v;   // exclusive
}

__global__ void scanC_kernel(int Nn)
{
    __shared__ int sh[256];
    int t = threadIdx.x;
    int i = blockIdx.x * 256 + t;
    int v = (i < Nn) ? g_dcnt[i] : 0;
    sh[t] = v;
    __syncthreads();
    for (int off = 1; off < 256; off <<= 1) {
        int x = (t >= off) ? sh[t - off] : 0;
        __syncthreads();
        sh[t] += x;
        __syncthreads();
    }
    int excl = sh[t] - v + g_partial[blockIdx.x];
    if (i < Nn) { g_rowptr[i] = excl; g_fill[i] = excl; }
    if (i == Nn - 1) g_rowptr[Nn] = excl + v;
}

__global__ void fill_kernel(const int* __restrict__ ei, int E)
{
    int i = blockIdx.x * blockDim.x + threadIdx.x;
    if (i >= E) return;
    int d = ei[E + i];
    int slot = atomicAdd(&g_fill[d], 1);
    g_eidx[slot] = ei[i];
}

// ---------------------------------------------------------------------------
// Gather-only aggregation: one warp per node, float4 per lane. Accumulates
// neighbor rows in registers, writes the MEAN (plain STG, no atomics).
// USE_BN: by linearity, mean(BN(h)) = scale*mean(h)+shift for deg>0.
// ---------------------------------------------------------------------------
template <int USE_BN>
__global__ void agg_kernel(const float* __restrict__ feat, int Nn)
{
    int node = (blockIdx.x * blockDim.x + threadIdx.x) >> 5;
    int lane = threadIdx.x & 31;
    if (node >= Nn) return;
    int e0 = __ldg(&g_rowptr[node]);
    int e1 = __ldg(&g_rowptr[node + 1]);

    float4 acc = make_float4(0.f, 0.f, 0.f, 0.f);
    int e = e0;
    for (; e + 1 < e1; e += 2) {
        int s0 = __ldg(&g_eidx[e]);
        int s1 = __ldg(&g_eidx[e + 1]);
        float4 v0 = __ldg((const float4*)(feat + (size_t)s0 * D) + lane);
        float4 v1 = __ldg((const float4*)(feat + (size_t)s1 * D) + lane);
        acc.x += v0.x + v1.x; acc.y += v0.y + v1.y;
        acc.z += v0.z + v1.z; acc.w += v0.w + v1.w;
    }
    if (e < e1) {
        int s0 = __ldg(&g_eidx[e]);
        float4 v0 = __ldg((const float4*)(feat + (size_t)s0 * D) + lane);
        acc.x += v0.x; acc.y += v0.y; acc.z += v0.z; acc.w += v0.w;
    }
    int deg = e1 - e0;
    float inv = (deg > 0) ? (1.0f / (float)deg) : 0.0f;
    float4 out;
    out.x = acc.x * inv; out.y = acc.y * inv;
    out.z = acc.z * inv; out.w = acc.w * inv;
    if (USE_BN && deg > 0) {
        float4 sc = ((const float4*)g_scale)[lane];
        float4 sf = ((const float4*)g_shift)[lane];
        out.x = fmaf(out.x, sc.x, sf.x);
        out.y = fmaf(out.y, sc.y, sf.y);
        out.z = fmaf(out.z, sc.z, sf.z);
        out.w = fmaf(out.w, sc.w, sf.w);
    }
    ((float4*)(g_agg + (size_t)node * D))[lane] = out;
}

// ---------------------------------------------------------------------------
// Fused SAGE layer:  out = [mean | xin'] @ [Wl ; Wr] + b
// (LAYER==2: xin' = BN(xin) applied on the fly from g_scale/g_shift)
// then row-wise L2 normalize. LAYER==1: relu, store h_pre, accumulate BN
// sum/sumsq. LAYER==2: store embed to d_out, compute fc preds.
// 256 threads, 128x128 output tile, 8x8 register tile per thread.
// A smem tile stored K-major [16][136] so the 8 a-loads are 2x LDS.128.
// ---------------------------------------------------------------------------
template <int LAYER>
__global__ __launch_bounds__(256, 2)
void sage_kernel(const float* __restrict__ xin,
                 const float* __restrict__ Wl,
                 const float* __restrict__ Wr,
                 const float* __restrict__ bias,
                 const float* __restrict__ fcW,
                 const float* __restrict__ fcb,
                 float* __restrict__ outh,    // layer1: h_pre
                 float* __restrict__ oute,    // layer2: embed (d_out + N)
                 float* __restrict__ outp,    // layer2: preds (d_out)
                 int Nn)
{
    __shared__ float AsT[16][136];  // A' tile [kk][row], padded
    __shared__ float Bs[16][D];     // B' tile [kk][col]
    __shared__ float RowInv[D];     // inv_norm for epilogue
    __shared__ float ScS[D], ShS[D];

    float* AsF = &AsT[0][0];        // epilogue scratch alias: [r*17+t]

    const int tid = threadIdx.x;
    const int tx = tid & 15;        // col group: cols tx + j*16
    const int ty = tid >> 4;        // row group: rows ty*8 + i
    const int row0 = blockIdx.x * D;

    if (LAYER == 2 && tid < D) { ScS[tid] = g_scale[tid]; ShS[tid] = g_shift[tid]; }
    if (LAYER == 2) __syncthreads();

    float acc[8][8];
#pragma unroll
    for (int i = 0; i < 8; i++)
#pragma unroll
        for (int j = 0; j < 8; j++) acc[i][j] = 0.f;

    const int lr  = tid >> 1;        // row this thread loads for A
    const int kk0 = (tid & 1) * 8;   // k sub-offset
    const int grow = row0 + lr;
    const bool rok = grow < Nn;

    const int bkk = tid >> 4;        // B tile row this thread loads
    const int bc  = tx * 8;          // B tile col base

    for (int kc = 0; kc < KK; kc += 16) {
        float av[8];
        if (rok) {
            if (kc < D) {
                const float4* p = (const float4*)(g_agg + (size_t)grow * D + kc + kk0);
                float4 v0 = p[0], v1 = p[1];
                av[0] = v0.x; av[1] = v0.y; av[2] = v0.z; av[3] = v0.w;
                av[4] = v1.x; av[5] = v1.y; av[6] = v1.z; av[7] = v1.w;
            } else {
                const float4* p = (const float4*)(xin + (size_t)grow * D + (kc - D) + kk0);
                float4 v0 = p[0], v1 = p[1];
                av[0] = v0.x; av[1] = v0.y; av[2] = v0.z; av[3] = v0.w;
                av[4] = v1.x; av[5] = v1.y; av[6] = v1.z; av[7] = v1.w;
                if (LAYER == 2) {
                    int c0 = kc - D + kk0;
#pragma unroll
                    for (int i = 0; i < 8; i++)
                        av[i] = fmaf(av[i], ScS[c0 + i], ShS[c0 + i]);
                }
            }
        } else {
#pragma unroll
            for (int i = 0; i < 8; i++) av[i] = 0.f;
        }
        int bk = kc + bkk;
        const float* wsrc = (bk < D) ? (Wl + (size_t)bk * D + bc)
                                     : (Wr + (size_t)(bk - D) * D + bc);
        float4 b0 = ((const float4*)wsrc)[0];
        float4 b1 = ((const float4*)wsrc)[1];

        __syncthreads();
#pragma unroll
        for (int i = 0; i < 8; i++) AsT[kk0 + i][lr] = av[i];
        *((float4*)&Bs[bkk][bc])     = b0;
        *((float4*)&Bs[bkk][bc + 4]) = b1;
        __syncthreads();

#pragma unroll
        for (int kk = 0; kk < 16; kk++) {
            float a[8], b[8];
            *((float4*)&a[0]) = *((const float4*)&AsT[kk][ty * 8]);
            *((float4*)&a[4]) = *((const float4*)&AsT[kk][ty * 8 + 4]);
#pragma unroll
            for (int j = 0; j < 8; j++) b[j] = Bs[kk][tx + j * 16];
#pragma unroll
            for (int i = 0; i < 8; i++)
#pragma unroll
                for (int j = 0; j < 8; j++)
                    acc[i][j] = fmaf(a[i], b[j], acc[i][j]);
        }
    }

    // + bias
#pragma unroll
    for (int j = 0; j < 8; j++) {
        float bb = bias[tx + j * 16];
#pragma unroll
        for (int i = 0; i < 8; i++) acc[i][j] += bb;
    }

    // row-wise L2 norm: partial sumsq -> smem reduce (scratch = AsF[r*17+t])
    __syncthreads();
#pragma unroll
    for (int i = 0; i < 8; i++) {
        float s = 0.f;
#pragma unroll
        for (int j = 0; j < 8; j++) s = fmaf(acc[i][j], acc[i][j], s);
        AsF[(ty * 8 + i) * 17 + tx] = s;
    }
    __syncthreads();
    if (tid < D) {
        float s = 0.f;
#pragma unroll
        for (int t = 0; t < 16; t++) s += AsF[tid * 17 + t];
        RowInv[tid] = 1.0f / fmaxf(sqrtf(s), 1e-12f);
    }
    __syncthreads();

    float val[8][8];
#pragma unroll
    for (int i = 0; i < 8; i++) {
        float iv = RowInv[ty * 8 + i];
        bool ok = (row0 + ty * 8 + i) < Nn;
#pragma unroll
        for (int j = 0; j < 8; j++) {
            float v = acc[i][j] * iv;
            if (LAYER == 1) v = fmaxf(v, 0.f);
            val[i][j] = ok ? v : 0.f;
        }
    }

    if (LAYER == 1) {
#pragma unroll
        for (int i = 0; i < 8; i++) {
            int r = row0 + ty * 8 + i;
            if (r < Nn) {
#pragma unroll
                for (int j = 0; j < 8; j++)
                    outh[(size_t)r * D + tx + j * 16] = val[i][j];
            }
        }
        // BN column sums (per-block partial -> atomic)
        __syncthreads();
#pragma unroll
        for (int j = 0; j < 8; j++) {
            float s = 0.f;
#pragma unroll
            for (int i = 0; i < 8; i++) s += val[i][j];
            Bs[ty][tx + j * 16] = s;
        }
        __syncthreads();
        if (tid < D) {
            float s = 0.f;
#pragma unroll
            for (int t = 0; t < 16; t++) s += Bs[t][tid];
            atomicAdd(g_bnsum + tid, s);
        }
        __syncthreads();
#pragma unroll
        for (int j = 0; j < 8; j++) {
            float s = 0.f;
#pragma unroll
            for (int i = 0; i < 8; i++) s = fmaf(val[i][j], val[i][j], s);
            Bs[ty][tx + j * 16] = s;
        }
        __syncthreads();
        if (tid < D) {
            float s = 0.f;
#pragma unroll
            for (int t = 0; t < 16; t++) s += Bs[t][tid];
            atomicAdd(g_bnsumsq + tid, s);
        }
    } else {
#pragma unroll
        for (int i = 0; i < 8; i++) {
            int r = row0 + ty * 8 + i;
            if (r < Nn) {
#pragma unroll
                for (int j = 0; j < 8; j++)
                    oute[(size_t)r * D + tx + j * 16] = val[i][j];
            }
        }
        // preds = embed[:, :64] @ fcW + fcb  (cols tx + j*16, j<4 => col < 64)
        float fw[4];
#pragma unroll
        for (int j = 0; j < 4; j++) fw[j] = fcW[tx + j * 16];
        __syncthreads();
#pragma unroll
        for (int i = 0; i < 8; i++) {
            float s = 0.f;
#pragma unroll
            for (int j = 0; j < 4; j++) s = fmaf(val[i][j], fw[j], s);
            AsF[(ty * 8 + i) * 17 + tx] = s;
        }
        __syncthreads();
        if (tid < D) {
            int r = row0 + tid;
            if (r < Nn) {
                float s = 0.f;
#pragma unroll
                for (int t = 0; t < 16; t++) s += AsF[tid * 17 + t];
                outp[r] = s + fcb[0];
            }
        }
    }
}

// ---------------------------------------------------------------------------
__global__ void bnstat_kernel(const float* __restrict__ gamma,
                              const float* __restrict__ beta, float invN)
{
    int c = threadIdx.x;
    float mu  = g_bnsum[c] * invN;
    float var = g_bnsumsq[c] * invN - mu * mu;
    float s = gamma[c] * rsqrtf(var + 1e-5f);
    g_scale[c] = s;
    g_shift[c] = beta[c] - mu * s;
}

// ---------------------------------------------------------------------------
extern "C" void kernel_launch(void* const* d_in, const int* in_sizes, int n_in,
                              void* d_out, int out_size)
{
    const float* x   = (const float*)d_in[0];
    const int*   ei  = (const int*)  d_in[1];
    const float* W1l = (const float*)d_in[2];
    const float* b1l = (const float*)d_in[3];
    const float* W1r = (const float*)d_in[4];
    const float* bng = (const float*)d_in[5];
    const float* bnb = (const float*)d_in[6];
    const float* W2l = (const float*)d_in[7];
    const float* b2l = (const float*)d_in[8];
    const float* W2r = (const float*)d_in[9];
    const float* fcW = (const float*)d_in[10];
    const float* fcb = (const float*)d_in[11];

    int Nn = in_sizes[0] / D;
    int E  = in_sizes[1] / 2;

    float* out   = (float*)d_out;
    float* pred  = out;          // [N]
    float* embed = out + Nn;     // [N,128]

    void *cnt_p, *sum_p, *sq_p, *h_pv;
    cudaGetSymbolAddress(&cnt_p, g_dcnt);
    cudaGetSymbolAddress(&sum_p, g_bnsum);
    cudaGetSymbolAddress(&sq_p,  g_bnsumsq);
    cudaGetSymbolAddress(&h_pv,  g_h);
    float* h_p = (float*)h_pv;

    cudaMemsetAsync(cnt_p, 0, (size_t)Nn * sizeof(int), 0);
    cudaMemsetAsync(sum_p, 0, D * sizeof(float), 0);
    cudaMemsetAsync(sq_p,  0, D * sizeof(float), 0);

    // CSR build (shared by both layers)
    const int eb = (E + 255) / 256;
    const int nb = (Nn + 255) / 256;
    hist_kernel<<<eb, 256>>>(ei, E);
    scanA_kernel<<<nb, 256>>>(Nn);
    scanB_kernel<<<1, 512>>>(nb);
    scanC_kernel<<<nb, 256>>>(Nn);
    fill_kernel<<<eb, 256>>>(ei, E);

    const int ab = (Nn * 32 + 255) / 256;   // warp per node
    const int gblocks = (Nn + D - 1) / D;

    agg_kernel<0><<<ab, 256>>>(x, Nn);
    sage_kernel<1><<<gblocks, 256>>>(x, W1l, W1r, b1l, nullptr, nullptr,
                                     h_p, nullptr, nullptr, Nn);

    bnstat_kernel<<<1, D>>>(bng, bnb, 1.0f / (float)Nn);

    agg_kernel<1><<<ab, 256>>>(h_p, Nn);    // BN fused via linearity
    sage_kernel<2><<<gblocks, 256>>>(h_p, W2l, W2r, b2l, fcW, fcb,
                                     nullptr, embed, pred, Nn);
}

// round 11
// speedup vs baseline: 1.3616x; 1.0625x over previous
#include <cuda_runtime.h>
#include <math.h>

// Problem constants (shapes fixed by the dataset)
#define NN 100000
#define EE 600000
#define D  128
#define KK 256   // concat-K: [mean | x] against [W_l ; W_r]

// Packed f32x2 helpers (sm_100+): FFMA2 is only reachable via PTX fma.rn.f32x2
#define FMA2(acc, a2, b2) \
    asm("fma.rn.f32x2 %0, %1, %2, %0;" : "+l"(acc) : "l"(a2), "l"(b2))
#define ADD2(acc, b2) \
    asm("add.rn.f32x2 %0, %0, %1;" : "+l"(acc) : "l"(b2))
#define PACK2DUP(dst, x) \
    asm("mov.b64 %0, {%1, %1};" : "=l"(dst) : "r"(__float_as_uint(x)))
#define UNPACK2(lo, hi, v) do { unsigned int _ul, _uh;                      \
    asm("mov.b64 {%0, %1}, %2;" : "=r"(_ul), "=r"(_uh) : "l"(v));           \
    lo = __uint_as_float(_ul); hi = __uint_as_float(_uh); } while (0)

// Scratch (allocation-free rule: __device__ globals)
__device__ float g_agg[(size_t)NN * D];
__device__ float g_h[(size_t)NN * D];
__device__ float g_bnsum[D];
__device__ float g_bnsumsq[D];
__device__ float g_scale[D];
__device__ float g_shift[D];
// CSR scratch
__device__ int g_dcnt[NN];
__device__ int g_rowptr[NN + 1];
__device__ int g_fill[NN];
__device__ int g_eidx[EE];
__device__ int g_partial[512];

// ---------------------------------------------------------------------------
// CSR build: histogram -> exclusive scan (3 kernels) -> fill
// ---------------------------------------------------------------------------
__global__ void hist_kernel(const int* __restrict__ ei, int E)
{
    int i = blockIdx.x * blockDim.x + threadIdx.x;
    if (i < E) atomicAdd(&g_dcnt[ei[E + i]], 1);
}

__global__ void scanA_kernel(int Nn)
{
    __shared__ int sh[256];
    int i = blockIdx.x * 256 + threadIdx.x;
    sh[threadIdx.x] = (i < Nn) ? g_dcnt[i] : 0;
    __syncthreads();
    for (int off = 128; off > 0; off >>= 1) {
        if (threadIdx.x < off) sh[threadIdx.x] += sh[threadIdx.x + off];
        __syncthreads();
    }
    if (threadIdx.x == 0) g_partial[blockIdx.x] = sh[0];
}

__global__ void scanB_kernel(int nb)   // single block, 512 threads
{
    __shared__ int sh[512];
    int t = threadIdx.x;
    int v = (t < nb) ? g_partial[t] : 0;
    sh[t] = v;
    __syncthreads();
    for (int off = 1; off < 512; off <<= 1) {
        int x = (t >= off) ? sh[t - off] : 0;
        __syncthreads();
        sh[t] += x;
        __syncthreads();
    }
    if (t < nb) g_partial[t] = sh[t] - v;   // exclusive
}

__global__ void scanC_kernel(int Nn)
{
    __shared__ int sh[256];
    int t = threadIdx.x;
    int i = blockIdx.x * 256 + t;
    int v = (i < Nn) ? g_dcnt[i] : 0;
    sh[t] = v;
    __syncthreads();
    for (int off = 1; off < 256; off <<= 1) {
        int x = (t >= off) ? sh[t - off] : 0;
        __syncthreads();
        sh[t] += x;
        __syncthreads();
    }
    int excl = sh[t] - v + g_partial[blockIdx.x];
    if (i < Nn) { g_rowptr[i] = excl; g_fill[i] = excl; }
    if (i == Nn - 1) g_rowptr[Nn] = excl + v;
}

__global__ void fill_kernel(const int* __restrict__ ei, int E)
{
    int i = blockIdx.x * blockDim.x + threadIdx.x;
    if (i >= E) return;
    int d = ei[E + i];
    int slot = atomicAdd(&g_fill[d], 1);
    g_eidx[slot] = ei[i];
}

// ---------------------------------------------------------------------------
// Gather-only aggregation: one warp per node, float4 per lane. Accumulates
// neighbor rows in registers, writes the MEAN (plain STG, no atomics).
// USE_BN: by linearity, mean(BN(h)) = scale*mean(h)+shift for deg>0.
// ---------------------------------------------------------------------------
template <int USE_BN>
__global__ void agg_kernel(const float* __restrict__ feat, int Nn)
{
    int node = (blockIdx.x * blockDim.x + threadIdx.x) >> 5;
    int lane = threadIdx.x & 31;
    if (node >= Nn) return;
    int e0 = __ldg(&g_rowptr[node]);
    int e1 = __ldg(&g_rowptr[node + 1]);

    float4 acc = make_float4(0.f, 0.f, 0.f, 0.f);
    int e = e0;
    for (; e + 1 < e1; e += 2) {
        int s0 = __ldg(&g_eidx[e]);
        int s1 = __ldg(&g_eidx[e + 1]);
        float4 v0 = __ldg((const float4*)(feat + (size_t)s0 * D) + lane);
        float4 v1 = __ldg((const float4*)(feat + (size_t)s1 * D) + lane);
        acc.x += v0.x + v1.x; acc.y += v0.y + v1.y;
        acc.z += v0.z + v1.z; acc.w += v0.w + v1.w;
    }
    if (e < e1) {
        int s0 = __ldg(&g_eidx[e]);
        float4 v0 = __ldg((const float4*)(feat + (size_t)s0 * D) + lane);
        acc.x += v0.x; acc.y += v0.y; acc.z += v0.z; acc.w += v0.w;
    }
    int deg = e1 - e0;
    float inv = (deg > 0) ? (1.0f / (float)deg) : 0.0f;
    float4 out;
    out.x = acc.x * inv; out.y = acc.y * inv;
    out.z = acc.z * inv; out.w = acc.w * inv;
    if (USE_BN && deg > 0) {
        float4 sc = ((const float4*)g_scale)[lane];
        float4 sf = ((const float4*)g_shift)[lane];
        out.x = fmaf(out.x, sc.x, sf.x);
        out.y = fmaf(out.y, sc.y, sf.y);
        out.z = fmaf(out.z, sc.z, sf.z);
        out.w = fmaf(out.w, sc.w, sf.w);
    }
    ((float4*)(g_agg + (size_t)node * D))[lane] = out;
}

// ---------------------------------------------------------------------------
// Fused SAGE layer with packed f32x2 (FFMA2) mainloop.
// out = [mean | xin'] @ [Wl ; Wr] + b, then row L2 normalize.
// LAYER==1: relu, store h_pre, accumulate BN sum/sumsq.
// LAYER==2: xin' = BN(xin) on the fly; store embed, compute fc preds.
// 256 threads, 128x128 tile. Per thread: 8 rows x 4 col-PAIRS.
// Thread columns: {tx*2 + jj*32, tx*2+1 + jj*32}, jj=0..3.
// ---------------------------------------------------------------------------
template <int LAYER>
__global__ __launch_bounds__(256, 2)
void sage_kernel(const float* __restrict__ xin,
                 const float* __restrict__ Wl,
                 const float* __restrict__ Wr,
                 const float* __restrict__ bias,
                 const float* __restrict__ fcW,
                 const float* __restrict__ fcb,
                 float* __restrict__ outh,    // layer1: h_pre
                 float* __restrict__ oute,    // layer2: embed (d_out + N)
                 float* __restrict__ outp,    // layer2: preds (d_out)
                 int Nn)
{
    __shared__ float AsT[16][136];  // A' tile [kk][row], padded
    __shared__ float Bs[16][D];     // B' tile [kk][col]
    __shared__ float RowInv[D];     // inv_norm for epilogue
    __shared__ float ScS[D], ShS[D];

    float* AsF = &AsT[0][0];        // epilogue scratch alias: [r*17+t]

    const int tid = threadIdx.x;
    const int tx = tid & 15;        // col-pair group
    const int ty = tid >> 4;        // row group: rows ty*8 + i
    const int row0 = blockIdx.x * D;

    if (LAYER == 2 && tid < D) { ScS[tid] = g_scale[tid]; ShS[tid] = g_shift[tid]; }
    if (LAYER == 2) __syncthreads();

    unsigned long long acc2[8][4];
#pragma unroll
    for (int i = 0; i < 8; i++)
#pragma unroll
        for (int jj = 0; jj < 4; jj++) acc2[i][jj] = 0ULL;

    const int lr  = tid >> 1;        // row this thread loads for A
    const int kk0 = (tid & 1) * 8;   // k sub-offset
    const int grow = row0 + lr;
    const bool rok = grow < Nn;

    const int bkk = tid >> 4;        // B tile row this thread loads
    const int bc  = tx * 8;          // B tile col base

    for (int kc = 0; kc < KK; kc += 16) {
        float av[8];
        if (rok) {
            if (kc < D) {
                const float4* p = (const float4*)(g_agg + (size_t)grow * D + kc + kk0);
                float4 v0 = p[0], v1 = p[1];
                av[0] = v0.x; av[1] = v0.y; av[2] = v0.z; av[3] = v0.w;
                av[4] = v1.x; av[5] = v1.y; av[6] = v1.z; av[7] = v1.w;
            } else {
                const float4* p = (const float4*)(xin + (size_t)grow * D + (kc - D) + kk0);
                float4 v0 = p[0], v1 = p[1];
                av[0] = v0.x; av[1] = v0.y; av[2] = v0.z; av[3] = v0.w;
                av[4] = v1.x; av[5] = v1.y; av[6] = v1.z; av[7] = v1.w;
                if (LAYER == 2) {
                    int c0 = kc - D + kk0;
#pragma unroll
                    for (int i = 0; i < 8; i++)
                        av[i] = fmaf(av[i], ScS[c0 + i], ShS[c0 + i]);
                }
            }
        } else {
#pragma unroll
            for (int i = 0; i < 8; i++) av[i] = 0.f;
        }
        int bk = kc + bkk;
        const float* wsrc = (bk < D) ? (Wl + (size_t)bk * D + bc)
                                     : (Wr + (size_t)(bk - D) * D + bc);
        float4 b0 = ((const float4*)wsrc)[0];
        float4 b1 = ((const float4*)wsrc)[1];

        __syncthreads();
#pragma unroll
        for (int i = 0; i < 8; i++) AsT[kk0 + i][lr] = av[i];
        *((float4*)&Bs[bkk][bc])     = b0;
        *((float4*)&Bs[bkk][bc + 4]) = b1;
        __syncthreads();

#pragma unroll
        for (int kk = 0; kk < 16; kk++) {
            float a[8];
            *((float4*)&a[0]) = *((const float4*)&AsT[kk][ty * 8]);
            *((float4*)&a[4]) = *((const float4*)&AsT[kk][ty * 8 + 4]);
            unsigned long long ap[8];
#pragma unroll
            for (int i = 0; i < 8; i++) PACK2DUP(ap[i], a[i]);
            unsigned long long bp[4];
#pragma unroll
            for (int jj = 0; jj < 4; jj++)
                bp[jj] = *(const unsigned long long*)&Bs[kk][tx * 2 + jj * 32];
#pragma unroll
            for (int i = 0; i < 8; i++)
#pragma unroll
                for (int jj = 0; jj < 4; jj++)
                    FMA2(acc2[i][jj], ap[i], bp[jj]);
        }
    }

    // + bias (packed)
#pragma unroll
    for (int jj = 0; jj < 4; jj++) {
        unsigned long long bb2 = *(const unsigned long long*)(bias + tx * 2 + jj * 32);
#pragma unroll
        for (int i = 0; i < 8; i++) ADD2(acc2[i][jj], bb2);
    }

    // row-wise L2 norm: partial sumsq -> smem reduce (scratch = AsF[r*17+t])
    __syncthreads();
#pragma unroll
    for (int i = 0; i < 8; i++) {
        float s = 0.f;
#pragma unroll
        for (int jj = 0; jj < 4; jj++) {
            float lo, hi;
            UNPACK2(lo, hi, acc2[i][jj]);
            s = fmaf(lo, lo, s);
            s = fmaf(hi, hi, s);
        }
        AsF[(ty * 8 + i) * 17 + tx] = s;
    }
    __syncthreads();
    if (tid < D) {
        float s = 0.f;
#pragma unroll
        for (int t = 0; t < 16; t++) s += AsF[tid * 17 + t];
        RowInv[tid] = 1.0f / fmaxf(sqrtf(s), 1e-12f);
    }
    __syncthreads();

    float val[8][8];    // val[i][jj*2+h], column = tx*2 + jj*32 + h
#pragma unroll
    for (int i = 0; i < 8; i++) {
        float iv = RowInv[ty * 8 + i];
        bool ok = (row0 + ty * 8 + i) < Nn;
#pragma unroll
        for (int jj = 0; jj < 4; jj++) {
            float lo, hi;
            UNPACK2(lo, hi, acc2[i][jj]);
            lo *= iv; hi *= iv;
            if (LAYER == 1) { lo = fmaxf(lo, 0.f); hi = fmaxf(hi, 0.f); }
            val[i][jj * 2]     = ok ? lo : 0.f;
            val[i][jj * 2 + 1] = ok ? hi : 0.f;
        }
    }

    if (LAYER == 1) {
#pragma unroll
        for (int i = 0; i < 8; i++) {
            int r = row0 + ty * 8 + i;
            if (r < Nn) {
#pragma unroll
                for (int jj = 0; jj < 4; jj++)
                    *(float2*)(outh + (size_t)r * D + tx * 2 + jj * 32) =
                        make_float2(val[i][jj * 2], val[i][jj * 2 + 1]);
            }
        }
        // BN column sums (per-block partial -> atomic)
        __syncthreads();
#pragma unroll
        for (int jj = 0; jj < 4; jj++) {
            float s0 = 0.f, s1 = 0.f;
#pragma unroll
            for (int i = 0; i < 8; i++) { s0 += val[i][jj * 2]; s1 += val[i][jj * 2 + 1]; }
            *(float2*)&Bs[ty][tx * 2 + jj * 32] = make_float2(s0, s1);
        }
        __syncthreads();
        if (tid < D) {
            float s = 0.f;
#pragma unroll
            for (int t = 0; t < 16; t++) s += Bs[t][tid];
            atomicAdd(g_bnsum + tid, s);
        }
        __syncthreads();
#pragma unroll
        for (int jj = 0; jj < 4; jj++) {
            float s0 = 0.f, s1 = 0.f;
#pragma unroll
            for (int i = 0; i < 8; i++) {
                s0 = fmaf(val[i][jj * 2],     val[i][jj * 2],     s0);
                s1 = fmaf(val[i][jj * 2 + 1], val[i][jj * 2 + 1], s1);
            }
            *(float2*)&Bs[ty][tx * 2 + jj * 32] = make_float2(s0, s1);
        }
        __syncthreads();
        if (tid < D) {
            float s = 0.f;
#pragma unroll
            for (int t = 0; t < 16; t++) s += Bs[t][tid];
            atomicAdd(g_bnsumsq + tid, s);
        }
    } else {
#pragma unroll
        for (int i = 0; i < 8; i++) {
            int r = row0 + ty * 8 + i;
            if (r < Nn) {
#pragma unroll
                for (int jj = 0; jj < 4; jj++)
                    *(float2*)(oute + (size_t)r * D + tx * 2 + jj * 32) =
                        make_float2(val[i][jj * 2], val[i][jj * 2 + 1]);
            }
        }
        // preds = embed[:, :64] @ fcW + fcb (cols < 64 <=> jj < 2)
        float fw[4];
        fw[0] = fcW[tx * 2];      fw[1] = fcW[tx * 2 + 1];
        fw[2] = fcW[tx * 2 + 32]; fw[3] = fcW[tx * 2 + 33];
        __syncthreads();
#pragma unroll
        for (int i = 0; i < 8; i++) {
            float s = val[i][0] * fw[0] + val[i][1] * fw[1]
                    + val[i][2] * fw[2] + val[i][3] * fw[3];
            AsF[(ty * 8 + i) * 17 + tx] = s;
        }
        __syncthreads();
        if (tid < D) {
            int r = row0 + tid;
            if (r < Nn) {
                float s = 0.f;
#pragma unroll
                for (int t = 0; t < 16; t++) s += AsF[tid * 17 + t];
                outp[r] = s + fcb[0];
            }
        }
    }
}

// ---------------------------------------------------------------------------
__global__ void bnstat_kernel(const float* __restrict__ gamma,
                              const float* __restrict__ beta, float invN)
{
    int c = threadIdx.x;
    float mu  = g_bnsum[c] * invN;
    float var = g_bnsumsq[c] * invN - mu * mu;
    float s = gamma[c] * rsqrtf(var + 1e-5f);
    g_scale[c] = s;
    g_shift[c] = beta[c] - mu * s;
}

// ---------------------------------------------------------------------------
extern "C" void kernel_launch(void* const* d_in, const int* in_sizes, int n_in,
                              void* d_out, int out_size)
{
    const float* x   = (const float*)d_in[0];
    const int*   ei  = (const int*)  d_in[1];
    const float* W1l = (const float*)d_in[2];
    const float* b1l = (const float*)d_in[3];
    const float* W1r = (const float*)d_in[4];
    const float* bng = (const float*)d_in[5];
    const float* bnb = (const float*)d_in[6];
    const float* W2l = (const float*)d_in[7];
    const float* b2l = (const float*)d_in[8];
    const float* W2r = (const float*)d_in[9];
    const float* fcW = (const float*)d_in[10];
    const float* fcb = (const float*)d_in[11];

    int Nn = in_sizes[0] / D;
    int E  = in_sizes[1] / 2;

    float* out   = (float*)d_out;
    float* pred  = out;          // [N]
    float* embed = out + Nn;     // [N,128]

    void *cnt_p, *sum_p, *sq_p, *h_pv;
    cudaGetSymbolAddress(&cnt_p, g_dcnt);
    cudaGetSymbolAddress(&sum_p, g_bnsum);
    cudaGetSymbolAddress(&sq_p,  g_bnsumsq);
    cudaGetSymbolAddress(&h_pv,  g_h);
    float* h_p = (float*)h_pv;

    cudaMemsetAsync(cnt_p, 0, (size_t)Nn * sizeof(int), 0);
    cudaMemsetAsync(sum_p, 0, D * sizeof(float), 0);
    cudaMemsetAsync(sq_p,  0, D * sizeof(float), 0);

    // CSR build (shared by both layers)
    const int eb = (E + 255) / 256;
    const int nb = (Nn + 255) / 256;
    hist_kernel<<<eb, 256>>>(ei, E);
    scanA_kernel<<<nb, 256>>>(Nn);
    scanB_kernel<<<1, 512>>>(nb);
    scanC_kernel<<<nb, 256>>>(Nn);
    fill_kernel<<<eb, 256>>>(ei, E);

    const int ab = (Nn * 32 + 255) / 256;   // warp per node
    const int gblocks = (Nn + D - 1) / D;

    agg_kernel<0><<<ab, 256>>>(x, Nn);
    sage_kernel<1><<<gblocks, 256>>>(x, W1l, W1r, b1l, nullptr, nullptr,
                                     h_p, nullptr, nullptr, Nn);

    bnstat_kernel<<<1, D>>>(bng, bnb, 1.0f / (float)Nn);

    agg_kernel<1><<<ab, 256>>>(h_p, Nn);    // BN fused via linearity
    sage_kernel<2><<<gblocks, 256>>>(h_p, W2l, W2r, b2l, fcW, fcb,
                                     nullptr, embed, pred, Nn);
}